// round 12
// baseline (speedup 1.0000x reference)
#include <cuda_runtime.h>
#include <cuda_fp16.h>
#include <math.h>
#include <stdint.h>

// ---------------------------------------------------------------------------
// MoE: router -> scatter -> fp16 mma.sync grouped GEMM1(gelu) -> GEMM2 -> combine
// R10: single-pass fp16, 128x256 tile, 512 threads (16 warps 4Mx4N, warp 32x64
//      -> 4 warps/SMSP), 3-stage pipeline, race-free load-after-sync.
// ---------------------------------------------------------------------------
#define DD    1024
#define HH    4096
#define EE    8
#define NTOK  8192
#define BMT   128
#define MAXROWS (NTOK*2 + EE*BMT)   // 17408
#define BKH   64                    // K halves per chunk (128B rows, SW128)
#define NT    256                   // N cols per block

// stage: A 16K | B 32K = 48KB, 3 stages = 144KB
#define OFF_A   0
#define OFF_B   16384
#define STAGE   49152
#define NSTG    3
#define GEMM_SMEM (NSTG*STAGE)

// -------- scratch (device globals) -----------------------------------------
__device__ int   g_counts[EE];
__device__ int   g_cursor[EE];
__device__ int   g_off[EE + 1];
__device__ int   g_total;
__device__ int   g_tok[MAXROWS];
__device__ int   g_idx[NTOK * 2];
__device__ int   g_slot[NTOK * 2];
__device__ float g_p[NTOK * 2];

__device__ __align__(256) __half g_w1h[(size_t)EE * HH * DD];  // fp16(W1^T) [E][H][D]
__device__ __align__(256) __half g_w2h[(size_t)EE * DD * HH];  // fp16(W2^T) [E][D][H]
__device__ __align__(256) __half g_ah[(size_t)MAXROWS * DD];   // gathered fp16(x)
__device__ __align__(256) __half g_hh[(size_t)MAXROWS * HH];   // fp16(gelu(h))
__device__ __align__(256) float  g_o[(size_t)MAXROWS * DD];

// -------- PTX helpers -------------------------------------------------------
__device__ __forceinline__ uint32_t smem_u32(const void* p) {
    uint32_t a;
    asm("{ .reg .u64 t; cvta.to.shared.u64 t, %1; cvt.u32.u64 %0, t; }"
        : "=r"(a) : "l"(p));
    return a;
}

#define CP_A16(dst, src) \
    asm volatile("cp.async.cg.shared.global [%0], [%1], 16;" \
                 :: "r"(dst), "l"(src))
#define CP_COMMIT() asm volatile("cp.async.commit_group;" ::: "memory")
#define CP_WAIT1()  asm volatile("cp.async.wait_group 1;" ::: "memory")
#define CP_WAIT0()  asm volatile("cp.async.wait_group 0;" ::: "memory")

#define LDSM4(r0, r1, r2, r3, addr) \
    asm volatile("ldmatrix.sync.aligned.m8n8.x4.shared.b16 {%0,%1,%2,%3}, [%4];" \
                 : "=r"(r0), "=r"(r1), "=r"(r2), "=r"(r3) : "r"(addr))

#define HMMA(c, a, b) \
    asm volatile("mma.sync.aligned.m16n8k16.row.col.f32.f16.f16.f32 " \
                 "{%0,%1,%2,%3}, {%4,%5,%6,%7}, {%8,%9}, {%0,%1,%2,%3};" \
                 : "+f"((c)[0]), "+f"((c)[1]), "+f"((c)[2]), "+f"((c)[3]) \
                 : "r"((a)[0]), "r"((a)[1]), "r"((a)[2]), "r"((a)[3]), \
                   "r"((b)[0]), "r"((b)[1]))

// -------- small kernels ----------------------------------------------------
__global__ void init_k() {
    int i = blockIdx.x * blockDim.x + threadIdx.x;
    if (i < EE) g_counts[i] = 0;
    if (i < MAXROWS) g_tok[i] = 0;
}

__global__ void router_k(const float* __restrict__ x,
                         const float* __restrict__ Wg,
                         const float* __restrict__ bg) {
    int warp = (blockIdx.x * blockDim.x + threadIdx.x) >> 5;
    int lane = threadIdx.x & 31;
    if (warp >= NTOK) return;
    const float* xr = x + (size_t)warp * DD;
    float acc[EE];
#pragma unroll
    for (int e = 0; e < EE; e++) acc[e] = 0.f;
#pragma unroll
    for (int i = 0; i < DD / 32; i++) {
        float xv = xr[lane + 32 * i];
        const float* wr = Wg + (size_t)(lane + 32 * i) * EE;
#pragma unroll
        for (int e = 0; e < EE; e++) acc[e] += xv * wr[e];
    }
#pragma unroll
    for (int e = 0; e < EE; e++)
#pragma unroll
        for (int o = 16; o > 0; o >>= 1)
            acc[e] += __shfl_xor_sync(0xffffffffu, acc[e], o);
    if (lane == 0) {
        float l[EE];
        float m = -1e30f;
#pragma unroll
        for (int e = 0; e < EE; e++) { l[e] = acc[e] + bg[e]; m = fmaxf(m, l[e]); }
        float s = 0.f;
#pragma unroll
        for (int e = 0; e < EE; e++) s += expf(l[e] - m);
        int i0 = 0;
#pragma unroll
        for (int e = 1; e < EE; e++) if (l[e] > l[i0]) i0 = e;
        int i1 = (i0 == 0) ? 1 : 0;
#pragma unroll
        for (int e = 0; e < EE; e++) if (e != i0 && l[e] > l[i1]) i1 = e;
        g_idx[warp * 2 + 0] = i0;  g_p[warp * 2 + 0] = expf(l[i0] - m) / s;
        g_idx[warp * 2 + 1] = i1;  g_p[warp * 2 + 1] = expf(l[i1] - m) / s;
        atomicAdd(&g_counts[i0], 1);
        atomicAdd(&g_counts[i1], 1);
    }
}

__global__ void scan_k() {
    if (threadIdx.x == 0) {
        int off = 0;
        for (int e = 0; e < EE; e++) {
            g_off[e] = off;
            g_cursor[e] = off;
            off += (g_counts[e] + BMT - 1) / BMT * BMT;
        }
        g_off[EE] = off;
        g_total = off;
    }
}

__global__ void scatter_k() {
    int n = blockIdx.x * blockDim.x + threadIdx.x;
    if (n >= NTOK) return;
#pragma unroll
    for (int k = 0; k < 2; k++) {
        int e = g_idx[n * 2 + k];
        int pos = atomicAdd(&g_cursor[e], 1);
        g_tok[pos] = n;
        g_slot[n * 2 + k] = pos;
    }
}

// gather x rows per slot -> fp16
__global__ void pregather_k(const float* __restrict__ x) {
    int row = blockIdx.x, tid = threadIdx.x;
    int tok = g_tok[row];
    float4 v = ((const float4*)(x + (size_t)tok * DD))[tid];
    __half2 a; a.x = __float2half(v.x); a.y = __float2half(v.y);
    __half2 b; b.x = __float2half(v.z); b.y = __float2half(v.w);
    ((uint2*)(g_ah + (size_t)row * DD))[tid] =
        make_uint2(*(uint32_t*)&a, *(uint32_t*)&b);
}

// transpose in[e][R][C] fp32 -> out[e][C][R] fp16
__global__ void transconv_k(const float* __restrict__ in,
                            __half* __restrict__ oh,
                            int R, int C) {
    __shared__ float t[32][33];
    int e = blockIdx.z;
    const float* ip = in + (size_t)e * R * C;
    size_t ob = (size_t)e * R * C;
    int c0 = blockIdx.x * 32, r0 = blockIdx.y * 32;
#pragma unroll
    for (int i = threadIdx.y; i < 32; i += 8)
        t[i][threadIdx.x] = ip[(size_t)(r0 + i) * C + c0 + threadIdx.x];
    __syncthreads();
#pragma unroll
    for (int i = threadIdx.y; i < 32; i += 8) {
        size_t o = ob + (size_t)(c0 + i) * R + r0 + threadIdx.x;
        oh[o] = __float2half(t[threadIdx.x][i]);
    }
}

// ---------------------------------------------------------------------------
// fp16 mma.sync grouped GEMM.  C[128 x 256] per block, 512 threads.
// 16 warps: warp_m in {0..3} (32 rows), warp_n in {0..3} (64 cols).
// MODE 1: A=g_ah, out->g_hh (bias+gelu, fp16)
// MODE 2: A=g_hh, out->g_o (bias, fp32)
// ---------------------------------------------------------------------------
template <int KDIM>
__device__ __forceinline__ void load_stage(
    uint32_t stu,
    const __half* __restrict__ Ap, const __half* __restrict__ Bp,
    int kof, int tid) {
    // A: 128 rows x 8 chunks of 16B = 1024 items
#pragma unroll
    for (int it = 0; it < 2; ++it) {
        int idx = it * 512 + tid;
        int r = idx >> 3, c = idx & 7;
        uint32_t d = (uint32_t)(r * 128 + ((c ^ (r & 7)) << 4));
        CP_A16(stu + OFF_A + d, Ap + (size_t)r * KDIM + kof + c * 8);
    }
    // B: 256 rows x 8 chunks of 16B = 2048 items
#pragma unroll
    for (int it = 0; it < 4; ++it) {
        int idx = it * 512 + tid;
        int r = idx >> 3, c = idx & 7;
        uint32_t d = (uint32_t)(r * 128 + ((c ^ (r & 7)) << 4));
        CP_A16(stu + OFF_B + d, Bp + (size_t)r * KDIM + kof + c * 8);
    }
}

template <int KDIM, int NDIM, int MODE>
__global__ __launch_bounds__(512, 1)
void gemm_hmma(const __half* __restrict__ A, const __half* __restrict__ B,
               const float* __restrict__ bias) {
    const int row0 = blockIdx.y * BMT;
    if (row0 >= g_total) return;
    int e = 0;
    while (row0 >= g_off[e + 1]) ++e;
    const int nbase = blockIdx.x * NT;

    extern __shared__ __align__(128) char dsmem[];
    const uint32_t smem_u = smem_u32(dsmem);

    const int tid = threadIdx.x;
    const int lane = tid & 31;
    const int wid = tid >> 5;
    const int warp_m = wid & 3;   // 4 warps in M (32 rows each)
    const int warp_n = wid >> 2;  // 4 warps in N (64 cols each)

    const __half* Ap = A + (size_t)row0 * KDIM;
    const __half* Bp = B + ((size_t)e * NDIM + nbase) * KDIM;

    constexpr int NC = KDIM / BKH;

    // prologue: stages 0,1
#pragma unroll
    for (int p = 0; p < NSTG - 1; ++p) {
        load_stage<KDIM>(smem_u + p * STAGE, Ap, Bp, p * BKH, tid);
        CP_COMMIT();
    }

    float acc[2][8][4] = {};

    for (int kc = 0; kc < NC; ++kc) {
        // stage kc complete when <=1 younger group pending
        if (NC - 1 - kc >= 1) CP_WAIT1(); else CP_WAIT0();
        __syncthreads();   // also WAR-guards slot (kc+2)%3 == (kc-1)%3

        if (kc + NSTG - 1 < NC) {
            load_stage<KDIM>(smem_u + ((kc + NSTG - 1) % NSTG) * STAGE,
                             Ap, Bp, (kc + NSTG - 1) * BKH, tid);
            CP_COMMIT();
        }

        const uint32_t stu = smem_u + (kc % NSTG) * STAGE;
#pragma unroll
        for (int ks = 0; ks < 4; ++ks) {          // 4 x k16 within BK=64
            uint32_t a[2][4], b[8][2];
#pragma unroll
            for (int mi = 0; mi < 2; ++mi) {      // 2 m16 tiles over 32 rows
                int tile = lane >> 3;
                int row = warp_m * 32 + mi * 16 + (lane & 7) + ((tile & 1) << 3);
                int kc8 = ks * 2 + (tile >> 1);
                uint32_t off = (uint32_t)(row * 128 + ((kc8 ^ (row & 7)) << 4));
                LDSM4(a[mi][0], a[mi][1], a[mi][2], a[mi][3], stu + OFF_A + off);
            }
#pragma unroll
            for (int ng = 0; ng < 4; ++ng) {      // 8 n8 tiles over 64 cols
                int row = warp_n * 64 + ng * 16 + ((lane >> 4) << 3) + (lane & 7);
                int kc8 = ks * 2 + ((lane >> 3) & 1);
                uint32_t off = (uint32_t)(row * 128 + ((kc8 ^ (row & 7)) << 4));
                LDSM4(b[2 * ng][0], b[2 * ng][1], b[2 * ng + 1][0], b[2 * ng + 1][1],
                      stu + OFF_B + off);
            }
#pragma unroll
            for (int mi = 0; mi < 2; ++mi)
#pragma unroll
                for (int nt = 0; nt < 8; ++nt) HMMA(acc[mi][nt], a[mi], b[nt]);
        }
        __syncthreads();
    }

    // epilogue
    const int gr = lane >> 2;
    const int gc = (lane & 3) * 2;
#pragma unroll
    for (int mi = 0; mi < 2; ++mi) {
        const int rb = row0 + warp_m * 32 + mi * 16 + gr;
#pragma unroll
        for (int nt = 0; nt < 8; ++nt) {
            const int col = nbase + warp_n * 64 + nt * 8 + gc;
            const float2 bv = *(const float2*)(bias + (size_t)e * NDIM + col);
#pragma unroll
            for (int h = 0; h < 2; ++h) {   // rows gr and gr+8
                const int r = rb + h * 8;
                float u0 = acc[mi][nt][2 * h]     + bv.x;
                float u1 = acc[mi][nt][2 * h + 1] + bv.y;
                if (MODE == 1) {
                    u0 = 0.5f * u0 * (1.f + erff(u0 * 0.70710678118654752f));
                    u1 = 0.5f * u1 * (1.f + erff(u1 * 0.70710678118654752f));
                    __half2 hv; hv.x = __float2half(u0); hv.y = __float2half(u1);
                    *(__half2*)(g_hh + (size_t)r * HH + col) = hv;
                } else {
                    float2 ov; ov.x = u0; ov.y = u1;
                    *(float2*)(g_o + (size_t)r * NDIM + col) = ov;
                }
            }
        }
    }
}

// out[n,d] = p0 * g_o[slot0][d] + p1 * g_o[slot1][d]
__global__ void combine_k(float* __restrict__ out) {
    int i = blockIdx.x * blockDim.x + threadIdx.x;
    int n = i >> 8, d4 = i & 255;
    int   s0 = g_slot[n * 2 + 0], s1 = g_slot[n * 2 + 1];
    float p0 = g_p[n * 2 + 0],    p1 = g_p[n * 2 + 1];
    const float4 a = *(const float4*)&g_o[(size_t)s0 * DD + d4 * 4];
    const float4 b = *(const float4*)&g_o[(size_t)s1 * DD + d4 * 4];
    float4 r;
    r.x = p0 * a.x + p1 * b.x;
    r.y = p0 * a.y + p1 * b.y;
    r.z = p0 * a.z + p1 * b.z;
    r.w = p0 * a.w + p1 * b.w;
    ((float4*)out)[i] = r;
}

// ---------------------------------------------------------------------------
extern "C" void kernel_launch(void* const* d_in, const int* in_sizes, int n_in,
                              void* d_out, int out_size) {
    const float* x  = (const float*)d_in[0];
    const float* Wg = (const float*)d_in[1];
    const float* bg = (const float*)d_in[2];
    const float* W1 = (const float*)d_in[3];
    const float* b1 = (const float*)d_in[4];
    const float* W2 = (const float*)d_in[5];
    const float* b2 = (const float*)d_in[6];
    float* out = (float*)d_out;

    cudaFuncSetAttribute(gemm_hmma<DD, HH, 1>,
                         cudaFuncAttributeMaxDynamicSharedMemorySize, GEMM_SMEM);
    cudaFuncSetAttribute(gemm_hmma<HH, DD, 2>,
                         cudaFuncAttributeMaxDynamicSharedMemorySize, GEMM_SMEM);

    __half *w1h, *w2h, *ah, *hh;
    cudaGetSymbolAddress((void**)&w1h, g_w1h);
    cudaGetSymbolAddress((void**)&w2h, g_w2h);
    cudaGetSymbolAddress((void**)&ah,  g_ah);
    cudaGetSymbolAddress((void**)&hh,  g_hh);

    init_k<<<MAXROWS / 256, 256>>>();
    router_k<<<NTOK / 8, 256>>>(x, Wg, bg);
    scan_k<<<1, 32>>>();
    scatter_k<<<NTOK / 256, 256>>>();
    pregather_k<<<MAXROWS, 256>>>(x);
    // W1[e][D][H] -> [e][H][D] ; W2[e][H][D] -> [e][D][H]
    transconv_k<<<dim3(HH / 32, DD / 32, EE), dim3(32, 8)>>>(W1, w1h, DD, HH);
    transconv_k<<<dim3(DD / 32, HH / 32, EE), dim3(32, 8)>>>(W2, w2h, HH, DD);

    gemm_hmma<DD, HH, 1><<<dim3(HH / NT, MAXROWS / BMT), 512, GEMM_SMEM>>>(
        ah, w1h, b1);
    gemm_hmma<HH, DD, 2><<<dim3(DD / NT, MAXROWS / BMT), 512, GEMM_SMEM>>>(
        hh, w2h, b2);

    combine_k<<<(NTOK * DD / 4) / 256, 256>>>(out);
}

// round 15
// speedup vs baseline: 1.1029x; 1.1029x over previous
#include <cuda_runtime.h>
#include <cuda_fp16.h>
#include <math.h>
#include <stdint.h>

// ---------------------------------------------------------------------------
// MoE: router -> scatter -> fp16 mma.sync grouped GEMM1(gelu) -> GEMM2 -> combine
// R11: single-pass fp16, CTA 128x128 / 256 thr / 8 warps (4Mx2N, warp 32x64),
//      3-stage x 32KB smem -> 2 CTAs/SM for cross-CTA stall hiding.
// ---------------------------------------------------------------------------
#define DD    1024
#define HH    4096
#define EE    8
#define NTOK  8192
#define BMT   128
#define MAXROWS (NTOK*2 + EE*BMT)   // 17408
#define BKH   64                    // K halves per chunk (128B rows, SW128)
#define NT    128                   // N cols per block

// stage: A 16K | B 16K = 32KB, 3 stages = 96KB -> 2 CTAs/SM
#define OFF_A   0
#define OFF_B   16384
#define STAGE   32768
#define NSTG    3
#define GEMM_SMEM (NSTG*STAGE)

// -------- scratch (device globals) -----------------------------------------
__device__ int   g_counts[EE];
__device__ int   g_cursor[EE];
__device__ int   g_off[EE + 1];
__device__ int   g_total;
__device__ int   g_tok[MAXROWS];
__device__ int   g_idx[NTOK * 2];
__device__ int   g_slot[NTOK * 2];
__device__ float g_p[NTOK * 2];

__device__ __align__(256) __half g_w1h[(size_t)EE * HH * DD];  // fp16(W1^T) [E][H][D]
__device__ __align__(256) __half g_w2h[(size_t)EE * DD * HH];  // fp16(W2^T) [E][D][H]
__device__ __align__(256) __half g_ah[(size_t)MAXROWS * DD];   // gathered fp16(x)
__device__ __align__(256) __half g_hh[(size_t)MAXROWS * HH];   // fp16(gelu(h))
__device__ __align__(256) float  g_o[(size_t)MAXROWS * DD];

// -------- PTX helpers -------------------------------------------------------
__device__ __forceinline__ uint32_t smem_u32(const void* p) {
    uint32_t a;
    asm("{ .reg .u64 t; cvta.to.shared.u64 t, %1; cvt.u32.u64 %0, t; }"
        : "=r"(a) : "l"(p));
    return a;
}

#define CP_A16(dst, src) \
    asm volatile("cp.async.cg.shared.global [%0], [%1], 16;" \
                 :: "r"(dst), "l"(src))
#define CP_COMMIT() asm volatile("cp.async.commit_group;" ::: "memory")
#define CP_WAIT1()  asm volatile("cp.async.wait_group 1;" ::: "memory")
#define CP_WAIT0()  asm volatile("cp.async.wait_group 0;" ::: "memory")

#define LDSM4(r0, r1, r2, r3, addr) \
    asm volatile("ldmatrix.sync.aligned.m8n8.x4.shared.b16 {%0,%1,%2,%3}, [%4];" \
                 : "=r"(r0), "=r"(r1), "=r"(r2), "=r"(r3) : "r"(addr))

#define HMMA(c, a, b) \
    asm volatile("mma.sync.aligned.m16n8k16.row.col.f32.f16.f16.f32 " \
                 "{%0,%1,%2,%3}, {%4,%5,%6,%7}, {%8,%9}, {%0,%1,%2,%3};" \
                 : "+f"((c)[0]), "+f"((c)[1]), "+f"((c)[2]), "+f"((c)[3]) \
                 : "r"((a)[0]), "r"((a)[1]), "r"((a)[2]), "r"((a)[3]), \
                   "r"((b)[0]), "r"((b)[1]))

// -------- small kernels ----------------------------------------------------
__global__ void init_k() {
    int i = blockIdx.x * blockDim.x + threadIdx.x;
    if (i < EE) g_counts[i] = 0;
    if (i < MAXROWS) g_tok[i] = 0;
}

__global__ void router_k(const float* __restrict__ x,
                         const float* __restrict__ Wg,
                         const float* __restrict__ bg) {
    int warp = (blockIdx.x * blockDim.x + threadIdx.x) >> 5;
    int lane = threadIdx.x & 31;
    if (warp >= NTOK) return;
    const float* xr = x + (size_t)warp * DD;
    float acc[EE];
#pragma unroll
    for (int e = 0; e < EE; e++) acc[e] = 0.f;
#pragma unroll
    for (int i = 0; i < DD / 32; i++) {
        float xv = xr[lane + 32 * i];
        const float* wr = Wg + (size_t)(lane + 32 * i) * EE;
#pragma unroll
        for (int e = 0; e < EE; e++) acc[e] += xv * wr[e];
    }
#pragma unroll
    for (int e = 0; e < EE; e++)
#pragma unroll
        for (int o = 16; o > 0; o >>= 1)
            acc[e] += __shfl_xor_sync(0xffffffffu, acc[e], o);
    if (lane == 0) {
        float l[EE];
        float m = -1e30f;
#pragma unroll
        for (int e = 0; e < EE; e++) { l[e] = acc[e] + bg[e]; m = fmaxf(m, l[e]); }
        float s = 0.f;
#pragma unroll
        for (int e = 0; e < EE; e++) s += expf(l[e] - m);
        int i0 = 0;
#pragma unroll
        for (int e = 1; e < EE; e++) if (l[e] > l[i0]) i0 = e;
        int i1 = (i0 == 0) ? 1 : 0;
#pragma unroll
        for (int e = 0; e < EE; e++) if (e != i0 && l[e] > l[i1]) i1 = e;
        g_idx[warp * 2 + 0] = i0;  g_p[warp * 2 + 0] = expf(l[i0] - m) / s;
        g_idx[warp * 2 + 1] = i1;  g_p[warp * 2 + 1] = expf(l[i1] - m) / s;
        atomicAdd(&g_counts[i0], 1);
        atomicAdd(&g_counts[i1], 1);
    }
}

__global__ void scan_k() {
    if (threadIdx.x == 0) {
        int off = 0;
        for (int e = 0; e < EE; e++) {
            g_off[e] = off;
            g_cursor[e] = off;
            off += (g_counts[e] + BMT - 1) / BMT * BMT;
        }
        g_off[EE] = off;
        g_total = off;
    }
}

__global__ void scatter_k() {
    int n = blockIdx.x * blockDim.x + threadIdx.x;
    if (n >= NTOK) return;
#pragma unroll
    for (int k = 0; k < 2; k++) {
        int e = g_idx[n * 2 + k];
        int pos = atomicAdd(&g_cursor[e], 1);
        g_tok[pos] = n;
        g_slot[n * 2 + k] = pos;
    }
}

// gather x rows per slot -> fp16
__global__ void pregather_k(const float* __restrict__ x) {
    int row = blockIdx.x, tid = threadIdx.x;
    int tok = g_tok[row];
    float4 v = ((const float4*)(x + (size_t)tok * DD))[tid];
    __half2 a; a.x = __float2half(v.x); a.y = __float2half(v.y);
    __half2 b; b.x = __float2half(v.z); b.y = __float2half(v.w);
    ((uint2*)(g_ah + (size_t)row * DD))[tid] =
        make_uint2(*(uint32_t*)&a, *(uint32_t*)&b);
}

// transpose in[e][R][C] fp32 -> out[e][C][R] fp16
__global__ void transconv_k(const float* __restrict__ in,
                            __half* __restrict__ oh,
                            int R, int C) {
    __shared__ float t[32][33];
    int e = blockIdx.z;
    const float* ip = in + (size_t)e * R * C;
    size_t ob = (size_t)e * R * C;
    int c0 = blockIdx.x * 32, r0 = blockIdx.y * 32;
#pragma unroll
    for (int i = threadIdx.y; i < 32; i += 8)
        t[i][threadIdx.x] = ip[(size_t)(r0 + i) * C + c0 + threadIdx.x];
    __syncthreads();
#pragma unroll
    for (int i = threadIdx.y; i < 32; i += 8) {
        size_t o = ob + (size_t)(c0 + i) * R + r0 + threadIdx.x;
        oh[o] = __float2half(t[threadIdx.x][i]);
    }
}

// ---------------------------------------------------------------------------
// fp16 mma.sync grouped GEMM.  C[128 x 128] per block, 256 threads, 2 CTA/SM.
// 8 warps: warp_m in {0..3} (32 rows), warp_n in {0,1} (64 cols).
// MODE 1: A=g_ah, out->g_hh (bias+gelu, fp16)
// MODE 2: A=g_hh, out->g_o (bias, fp32)
// ---------------------------------------------------------------------------
template <int KDIM>
__device__ __forceinline__ void load_stage(
    uint32_t stu,
    const __half* __restrict__ Ap, const __half* __restrict__ Bp,
    int kof, int tid) {
    // A: 128 rows x 8 chunks of 16B = 1024 ops
#pragma unroll
    for (int it = 0; it < 4; ++it) {
        int idx = it * 256 + tid;
        int r = idx >> 3, c = idx & 7;
        uint32_t d = (uint32_t)(r * 128 + ((c ^ (r & 7)) << 4));
        CP_A16(stu + OFF_A + d, Ap + (size_t)r * KDIM + kof + c * 8);
    }
    // B: 128 rows x 8 chunks of 16B = 1024 ops
#pragma unroll
    for (int it = 0; it < 4; ++it) {
        int idx = it * 256 + tid;
        int r = idx >> 3, c = idx & 7;
        uint32_t d = (uint32_t)(r * 128 + ((c ^ (r & 7)) << 4));
        CP_A16(stu + OFF_B + d, Bp + (size_t)r * KDIM + kof + c * 8);
    }
}

template <int KDIM, int NDIM, int MODE>
__global__ __launch_bounds__(256, 2)
void gemm_hmma(const __half* __restrict__ A, const __half* __restrict__ B,
               const float* __restrict__ bias) {
    const int row0 = blockIdx.y * BMT;
    if (row0 >= g_total) return;
    int e = 0;
    while (row0 >= g_off[e + 1]) ++e;
    const int nbase = blockIdx.x * NT;

    extern __shared__ __align__(128) char dsmem[];
    const uint32_t smem_u = smem_u32(dsmem);

    const int tid = threadIdx.x;
    const int lane = tid & 31;
    const int wid = tid >> 5;
    const int warp_m = wid & 3;   // 4 warps in M (32 rows each)
    const int warp_n = wid >> 2;  // 2 warps in N (64 cols each)

    const __half* Ap = A + (size_t)row0 * KDIM;
    const __half* Bp = B + ((size_t)e * NDIM + nbase) * KDIM;

    constexpr int NC = KDIM / BKH;

    // prologue: stages 0,1
#pragma unroll
    for (int p = 0; p < NSTG - 1; ++p) {
        load_stage<KDIM>(smem_u + p * STAGE, Ap, Bp, p * BKH, tid);
        CP_COMMIT();
    }

    float acc[2][8][4] = {};

    for (int kc = 0; kc < NC; ++kc) {
        if (NC - 1 - kc >= 1) CP_WAIT1(); else CP_WAIT0();
        __syncthreads();   // stage kc ready AND stage kc-1 reads done

        // issue next stage AFTER the sync (overwrites oldest slot safely)
        if (kc + NSTG - 1 < NC) {
            load_stage<KDIM>(smem_u + ((kc + NSTG - 1) % NSTG) * STAGE,
                             Ap, Bp, (kc + NSTG - 1) * BKH, tid);
            CP_COMMIT();
        }

        const uint32_t stu = smem_u + (kc % NSTG) * STAGE;
#pragma unroll
        for (int ks = 0; ks < 4; ++ks) {          // 4 x k16 within BK=64
            uint32_t a[2][4], b[8][2];
#pragma unroll
            for (int mi = 0; mi < 2; ++mi) {      // 2 m16 tiles over 32 rows
                int tile = lane >> 3;
                int row = warp_m * 32 + mi * 16 + (lane & 7) + ((tile & 1) << 3);
                int kc8 = ks * 2 + (tile >> 1);
                uint32_t off = (uint32_t)(row * 128 + ((kc8 ^ (row & 7)) << 4));
                LDSM4(a[mi][0], a[mi][1], a[mi][2], a[mi][3], stu + OFF_A + off);
            }
#pragma unroll
            for (int ng = 0; ng < 4; ++ng) {      // 8 n8 tiles over 64 cols
                int row = warp_n * 64 + ng * 16 + ((lane >> 4) << 3) + (lane & 7);
                int kc8 = ks * 2 + ((lane >> 3) & 1);
                uint32_t off = (uint32_t)(row * 128 + ((kc8 ^ (row & 7)) << 4));
                LDSM4(b[2 * ng][0], b[2 * ng][1], b[2 * ng + 1][0], b[2 * ng + 1][1],
                      stu + OFF_B + off);
            }
#pragma unroll
            for (int mi = 0; mi < 2; ++mi)
#pragma unroll
                for (int nt = 0; nt < 8; ++nt) HMMA(acc[mi][nt], a[mi], b[nt]);
        }
        __syncthreads();
    }

    // epilogue
    const int gr = lane >> 2;
    const int gc = (lane & 3) * 2;
#pragma unroll
    for (int mi = 0; mi < 2; ++mi) {
        const int rb = row0 + warp_m * 32 + mi * 16 + gr;
#pragma unroll
        for (int nt = 0; nt < 8; ++nt) {
            const int col = nbase + warp_n * 64 + nt * 8 + gc;
            const float2 bv = *(const float2*)(bias + (size_t)e * NDIM + col);
#pragma unroll
            for (int h = 0; h < 2; ++h) {   // rows gr and gr+8
                const int r = rb + h * 8;
                float u0 = acc[mi][nt][2 * h]     + bv.x;
                float u1 = acc[mi][nt][2 * h + 1] + bv.y;
                if (MODE == 1) {
                    u0 = 0.5f * u0 * (1.f + erff(u0 * 0.70710678118654752f));
                    u1 = 0.5f * u1 * (1.f + erff(u1 * 0.70710678118654752f));
                    __half2 hv; hv.x = __float2half(u0); hv.y = __float2half(u1);
                    *(__half2*)(g_hh + (size_t)r * HH + col) = hv;
                } else {
                    float2 ov; ov.x = u0; ov.y = u1;
                    *(float2*)(g_o + (size_t)r * NDIM + col) = ov;
                }
            }
        }
    }
}

// out[n,d] = p0 * g_o[slot0][d] + p1 * g_o[slot1][d]
__global__ void combine_k(float* __restrict__ out) {
    int i = blockIdx.x * blockDim.x + threadIdx.x;
    int n = i >> 8, d4 = i & 255;
    int   s0 = g_slot[n * 2 + 0], s1 = g_slot[n * 2 + 1];
    float p0 = g_p[n * 2 + 0],    p1 = g_p[n * 2 + 1];
    const float4 a = *(const float4*)&g_o[(size_t)s0 * DD + d4 * 4];
    const float4 b = *(const float4*)&g_o[(size_t)s1 * DD + d4 * 4];
    float4 r;
    r.x = p0 * a.x + p1 * b.x;
    r.y = p0 * a.y + p1 * b.y;
    r.z = p0 * a.z + p1 * b.z;
    r.w = p0 * a.w + p1 * b.w;
    ((float4*)out)[i] = r;
}

// ---------------------------------------------------------------------------
extern "C" void kernel_launch(void* const* d_in, const int* in_sizes, int n_in,
                              void* d_out, int out_size) {
    const float* x  = (const float*)d_in[0];
    const float* Wg = (const float*)d_in[1];
    const float* bg = (const float*)d_in[2];
    const float* W1 = (const float*)d_in[3];
    const float* b1 = (const float*)d_in[4];
    const float* W2 = (const float*)d_in[5];
    const float* b2 = (const float*)d_in[6];
    float* out = (float*)d_out;

    cudaFuncSetAttribute(gemm_hmma<DD, HH, 1>,
                         cudaFuncAttributeMaxDynamicSharedMemorySize, GEMM_SMEM);
    cudaFuncSetAttribute(gemm_hmma<HH, DD, 2>,
                         cudaFuncAttributeMaxDynamicSharedMemorySize, GEMM_SMEM);

    __half *w1h, *w2h, *ah, *hh;
    cudaGetSymbolAddress((void**)&w1h, g_w1h);
    cudaGetSymbolAddress((void**)&w2h, g_w2h);
    cudaGetSymbolAddress((void**)&ah,  g_ah);
    cudaGetSymbolAddress((void**)&hh,  g_hh);

    init_k<<<MAXROWS / 256, 256>>>();
    router_k<<<NTOK / 8, 256>>>(x, Wg, bg);
    scan_k<<<1, 32>>>();
    scatter_k<<<NTOK / 256, 256>>>();
    pregather_k<<<MAXROWS, 256>>>(x);
    // W1[e][D][H] -> [e][H][D] ; W2[e][H][D] -> [e][D][H]
    transconv_k<<<dim3(HH / 32, DD / 32, EE), dim3(32, 8)>>>(W1, w1h, DD, HH);
    transconv_k<<<dim3(DD / 32, HH / 32, EE), dim3(32, 8)>>>(W2, w2h, HH, DD);

    gemm_hmma<DD, HH, 1><<<dim3(HH / NT, MAXROWS / BMT), 256, GEMM_SMEM>>>(
        ah, w1h, b1);
    gemm_hmma<HH, DD, 2><<<dim3(DD / NT, MAXROWS / BMT), 256, GEMM_SMEM>>>(
        hh, w2h, b2);

    combine_k<<<(NTOK * DD / 4) / 256, 256>>>(out);
}

// round 16
// speedup vs baseline: 1.1371x; 1.0310x over previous
#include <cuda_runtime.h>
#include <cuda_fp16.h>
#include <math.h>
#include <stdint.h>

// ---------------------------------------------------------------------------
// MoE: router -> scatter -> fp16 mma.sync grouped GEMM1(gelu) -> GEMM2 -> combine
// R12: CTA 128x128 / 128 thr / 4 warps (2Mx2N, warp tile 64x64) -> fragment
//      replication x2/x2, crossbar demand 96KB/chunk < MMA floor. 3-stage,
//      2 CTAs/SM.
// ---------------------------------------------------------------------------
#define DD    1024
#define HH    4096
#define EE    8
#define NTOK  8192
#define BMT   128
#define MAXROWS (NTOK*2 + EE*BMT)   // 17408
#define BKH   64                    // K halves per chunk (128B rows, SW128)
#define NT    128                   // N cols per block

// stage: A 16K | B 16K = 32KB, 3 stages = 96KB -> 2 CTAs/SM
#define OFF_A   0
#define OFF_B   16384
#define STAGE   32768
#define NSTG    3
#define GEMM_SMEM (NSTG*STAGE)

// -------- scratch (device globals) -----------------------------------------
__device__ int   g_counts[EE];
__device__ int   g_cursor[EE];
__device__ int   g_off[EE + 1];
__device__ int   g_total;
__device__ int   g_tok[MAXROWS];
__device__ int   g_idx[NTOK * 2];
__device__ int   g_slot[NTOK * 2];
__device__ float g_p[NTOK * 2];

__device__ __align__(256) __half g_w1h[(size_t)EE * HH * DD];  // fp16(W1^T) [E][H][D]
__device__ __align__(256) __half g_w2h[(size_t)EE * DD * HH];  // fp16(W2^T) [E][D][H]
__device__ __align__(256) __half g_ah[(size_t)MAXROWS * DD];   // gathered fp16(x)
__device__ __align__(256) __half g_hh[(size_t)MAXROWS * HH];   // fp16(gelu(h))
__device__ __align__(256) float  g_o[(size_t)MAXROWS * DD];

// -------- PTX helpers -------------------------------------------------------
__device__ __forceinline__ uint32_t smem_u32(const void* p) {
    uint32_t a;
    asm("{ .reg .u64 t; cvta.to.shared.u64 t, %1; cvt.u32.u64 %0, t; }"
        : "=r"(a) : "l"(p));
    return a;
}

#define CP_A16(dst, src) \
    asm volatile("cp.async.cg.shared.global [%0], [%1], 16;" \
                 :: "r"(dst), "l"(src))
#define CP_COMMIT() asm volatile("cp.async.commit_group;" ::: "memory")
#define CP_WAIT1()  asm volatile("cp.async.wait_group 1;" ::: "memory")
#define CP_WAIT0()  asm volatile("cp.async.wait_group 0;" ::: "memory")

#define LDSM4(r0, r1, r2, r3, addr) \
    asm volatile("ldmatrix.sync.aligned.m8n8.x4.shared.b16 {%0,%1,%2,%3}, [%4];" \
                 : "=r"(r0), "=r"(r1), "=r"(r2), "=r"(r3) : "r"(addr))

#define HMMA(c, a, b) \
    asm volatile("mma.sync.aligned.m16n8k16.row.col.f32.f16.f16.f32 " \
                 "{%0,%1,%2,%3}, {%4,%5,%6,%7}, {%8,%9}, {%0,%1,%2,%3};" \
                 : "+f"((c)[0]), "+f"((c)[1]), "+f"((c)[2]), "+f"((c)[3]) \
                 : "r"((a)[0]), "r"((a)[1]), "r"((a)[2]), "r"((a)[3]), \
                   "r"((b)[0]), "r"((b)[1]))

// -------- small kernels ----------------------------------------------------
__global__ void init_k() {
    int i = blockIdx.x * blockDim.x + threadIdx.x;
    if (i < EE) g_counts[i] = 0;
    if (i < MAXROWS) g_tok[i] = 0;
}

__global__ void router_k(const float* __restrict__ x,
                         const float* __restrict__ Wg,
                         const float* __restrict__ bg) {
    int warp = (blockIdx.x * blockDim.x + threadIdx.x) >> 5;
    int lane = threadIdx.x & 31;
    if (warp >= NTOK) return;
    const float* xr = x + (size_t)warp * DD;
    float acc[EE];
#pragma unroll
    for (int e = 0; e < EE; e++) acc[e] = 0.f;
#pragma unroll
    for (int i = 0; i < DD / 32; i++) {
        float xv = xr[lane + 32 * i];
        const float* wr = Wg + (size_t)(lane + 32 * i) * EE;
#pragma unroll
        for (int e = 0; e < EE; e++) acc[e] += xv * wr[e];
    }
#pragma unroll
    for (int e = 0; e < EE; e++)
#pragma unroll
        for (int o = 16; o > 0; o >>= 1)
            acc[e] += __shfl_xor_sync(0xffffffffu, acc[e], o);
    if (lane == 0) {
        float l[EE];
        float m = -1e30f;
#pragma unroll
        for (int e = 0; e < EE; e++) { l[e] = acc[e] + bg[e]; m = fmaxf(m, l[e]); }
        float s = 0.f;
#pragma unroll
        for (int e = 0; e < EE; e++) s += expf(l[e] - m);
        int i0 = 0;
#pragma unroll
        for (int e = 1; e < EE; e++) if (l[e] > l[i0]) i0 = e;
        int i1 = (i0 == 0) ? 1 : 0;
#pragma unroll
        for (int e = 0; e < EE; e++) if (e != i0 && l[e] > l[i1]) i1 = e;
        g_idx[warp * 2 + 0] = i0;  g_p[warp * 2 + 0] = expf(l[i0] - m) / s;
        g_idx[warp * 2 + 1] = i1;  g_p[warp * 2 + 1] = expf(l[i1] - m) / s;
        atomicAdd(&g_counts[i0], 1);
        atomicAdd(&g_counts[i1], 1);
    }
}

__global__ void scan_k() {
    if (threadIdx.x == 0) {
        int off = 0;
        for (int e = 0; e < EE; e++) {
            g_off[e] = off;
            g_cursor[e] = off;
            off += (g_counts[e] + BMT - 1) / BMT * BMT;
        }
        g_off[EE] = off;
        g_total = off;
    }
}

__global__ void scatter_k() {
    int n = blockIdx.x * blockDim.x + threadIdx.x;
    if (n >= NTOK) return;
#pragma unroll
    for (int k = 0; k < 2; k++) {
        int e = g_idx[n * 2 + k];
        int pos = atomicAdd(&g_cursor[e], 1);
        g_tok[pos] = n;
        g_slot[n * 2 + k] = pos;
    }
}

// gather x rows per slot -> fp16
__global__ void pregather_k(const float* __restrict__ x) {
    int row = blockIdx.x, tid = threadIdx.x;
    int tok = g_tok[row];
    float4 v = ((const float4*)(x + (size_t)tok * DD))[tid];
    __half2 a; a.x = __float2half(v.x); a.y = __float2half(v.y);
    __half2 b; b.x = __float2half(v.z); b.y = __float2half(v.w);
    ((uint2*)(g_ah + (size_t)row * DD))[tid] =
        make_uint2(*(uint32_t*)&a, *(uint32_t*)&b);
}

// transpose in[e][R][C] fp32 -> out[e][C][R] fp16
__global__ void transconv_k(const float* __restrict__ in,
                            __half* __restrict__ oh,
                            int R, int C) {
    __shared__ float t[32][33];
    int e = blockIdx.z;
    const float* ip = in + (size_t)e * R * C;
    size_t ob = (size_t)e * R * C;
    int c0 = blockIdx.x * 32, r0 = blockIdx.y * 32;
#pragma unroll
    for (int i = threadIdx.y; i < 32; i += 8)
        t[i][threadIdx.x] = ip[(size_t)(r0 + i) * C + c0 + threadIdx.x];
    __syncthreads();
#pragma unroll
    for (int i = threadIdx.y; i < 32; i += 8) {
        size_t o = ob + (size_t)(c0 + i) * R + r0 + threadIdx.x;
        oh[o] = __float2half(t[threadIdx.x][i]);
    }
}

// ---------------------------------------------------------------------------
// fp16 mma.sync grouped GEMM.  C[128 x 128] per block, 128 threads, 2 CTA/SM.
// 4 warps: warp_m in {0,1} (64 rows), warp_n in {0,1} (64 cols). Warp 64x64.
// MODE 1: A=g_ah, out->g_hh (bias+gelu, fp16)
// MODE 2: A=g_hh, out->g_o (bias, fp32)
// ---------------------------------------------------------------------------
template <int KDIM>
__device__ __forceinline__ void load_stage(
    uint32_t stu,
    const __half* __restrict__ Ap, const __half* __restrict__ Bp,
    int kof, int tid) {
    // A: 128 rows x 8 chunks of 16B = 1024 ops
#pragma unroll
    for (int it = 0; it < 8; ++it) {
        int idx = it * 128 + tid;
        int r = idx >> 3, c = idx & 7;
        uint32_t d = (uint32_t)(r * 128 + ((c ^ (r & 7)) << 4));
        CP_A16(stu + OFF_A + d, Ap + (size_t)r * KDIM + kof + c * 8);
    }
    // B: 128 rows x 8 chunks of 16B = 1024 ops
#pragma unroll
    for (int it = 0; it < 8; ++it) {
        int idx = it * 128 + tid;
        int r = idx >> 3, c = idx & 7;
        uint32_t d = (uint32_t)(r * 128 + ((c ^ (r & 7)) << 4));
        CP_A16(stu + OFF_B + d, Bp + (size_t)r * KDIM + kof + c * 8);
    }
}

template <int KDIM, int NDIM, int MODE>
__global__ __launch_bounds__(128, 2)
void gemm_hmma(const __half* __restrict__ A, const __half* __restrict__ B,
               const float* __restrict__ bias) {
    const int row0 = blockIdx.y * BMT;
    if (row0 >= g_total) return;
    int e = 0;
    while (row0 >= g_off[e + 1]) ++e;
    const int nbase = blockIdx.x * NT;

    extern __shared__ __align__(128) char dsmem[];
    const uint32_t smem_u = smem_u32(dsmem);

    const int tid = threadIdx.x;
    const int lane = tid & 31;
    const int wid = tid >> 5;
    const int warp_m = wid & 1;   // 2 warps in M (64 rows each)
    const int warp_n = wid >> 1;  // 2 warps in N (64 cols each)

    const __half* Ap = A + (size_t)row0 * KDIM;
    const __half* Bp = B + ((size_t)e * NDIM + nbase) * KDIM;

    constexpr int NC = KDIM / BKH;

    // prologue: stages 0,1
#pragma unroll
    for (int p = 0; p < NSTG - 1; ++p) {
        load_stage<KDIM>(smem_u + p * STAGE, Ap, Bp, p * BKH, tid);
        CP_COMMIT();
    }

    float acc[4][8][4] = {};

    for (int kc = 0; kc < NC; ++kc) {
        if (NC - 1 - kc >= 1) CP_WAIT1(); else CP_WAIT0();
        __syncthreads();   // stage kc ready AND stage kc-1 reads done

        // issue next stage AFTER the sync (overwrites oldest slot safely)
        if (kc + NSTG - 1 < NC) {
            load_stage<KDIM>(smem_u + ((kc + NSTG - 1) % NSTG) * STAGE,
                             Ap, Bp, (kc + NSTG - 1) * BKH, tid);
            CP_COMMIT();
        }

        const uint32_t stu = smem_u + (kc % NSTG) * STAGE;
#pragma unroll
        for (int ks = 0; ks < 4; ++ks) {          // 4 x k16 within BK=64
            uint32_t a[4][4], b[8][2];
#pragma unroll
            for (int mi = 0; mi < 4; ++mi) {      // 4 m16 tiles over 64 rows
                int tile = lane >> 3;
                int row = warp_m * 64 + mi * 16 + (lane & 7) + ((tile & 1) << 3);
                int kc8 = ks * 2 + (tile >> 1);
                uint32_t off = (uint32_t)(row * 128 + ((kc8 ^ (row & 7)) << 4));
                LDSM4(a[mi][0], a[mi][1], a[mi][2], a[mi][3], stu + OFF_A + off);
            }
#pragma unroll
            for (int ng = 0; ng < 4; ++ng) {      // 8 n8 tiles over 64 cols
                int row = warp_n * 64 + ng * 16 + ((lane >> 4) << 3) + (lane & 7);
                int kc8 = ks * 2 + ((lane >> 3) & 1);
                uint32_t off = (uint32_t)(row * 128 + ((kc8 ^ (row & 7)) << 4));
                LDSM4(b[2 * ng][0], b[2 * ng][1], b[2 * ng + 1][0], b[2 * ng + 1][1],
                      stu + OFF_B + off);
            }
#pragma unroll
            for (int mi = 0; mi < 4; ++mi)
#pragma unroll
                for (int nt = 0; nt < 8; ++nt) HMMA(acc[mi][nt], a[mi], b[nt]);
        }
        __syncthreads();
    }

    // epilogue
    const int gr = lane >> 2;
    const int gc = (lane & 3) * 2;
#pragma unroll
    for (int mi = 0; mi < 4; ++mi) {
        const int rb = row0 + warp_m * 64 + mi * 16 + gr;
#pragma unroll
        for (int nt = 0; nt < 8; ++nt) {
            const int col = nbase + warp_n * 64 + nt * 8 + gc;
            const float2 bv = *(const float2*)(bias + (size_t)e * NDIM + col);
#pragma unroll
            for (int h = 0; h < 2; ++h) {   // rows gr and gr+8
                const int r = rb + h * 8;
                float u0 = acc[mi][nt][2 * h]     + bv.x;
                float u1 = acc[mi][nt][2 * h + 1] + bv.y;
                if (MODE == 1) {
                    u0 = 0.5f * u0 * (1.f + erff(u0 * 0.70710678118654752f));
                    u1 = 0.5f * u1 * (1.f + erff(u1 * 0.70710678118654752f));
                    __half2 hv; hv.x = __float2half(u0); hv.y = __float2half(u1);
                    *(__half2*)(g_hh + (size_t)r * HH + col) = hv;
                } else {
                    float2 ov; ov.x = u0; ov.y = u1;
                    *(float2*)(g_o + (size_t)r * NDIM + col) = ov;
                }
            }
        }
    }
}

// out[n,d] = p0 * g_o[slot0][d] + p1 * g_o[slot1][d]
__global__ void combine_k(float* __restrict__ out) {
    int i = blockIdx.x * blockDim.x + threadIdx.x;
    int n = i >> 8, d4 = i & 255;
    int   s0 = g_slot[n * 2 + 0], s1 = g_slot[n * 2 + 1];
    float p0 = g_p[n * 2 + 0],    p1 = g_p[n * 2 + 1];
    const float4 a = *(const float4*)&g_o[(size_t)s0 * DD + d4 * 4];
    const float4 b = *(const float4*)&g_o[(size_t)s1 * DD + d4 * 4];
    float4 r;
    r.x = p0 * a.x + p1 * b.x;
    r.y = p0 * a.y + p1 * b.y;
    r.z = p0 * a.z + p1 * b.z;
    r.w = p0 * a.w + p1 * b.w;
    ((float4*)out)[i] = r;
}

// ---------------------------------------------------------------------------
extern "C" void kernel_launch(void* const* d_in, const int* in_sizes, int n_in,
                              void* d_out, int out_size) {
    const float* x  = (const float*)d_in[0];
    const float* Wg = (const float*)d_in[1];
    const float* bg = (const float*)d_in[2];
    const float* W1 = (const float*)d_in[3];
    const float* b1 = (const float*)d_in[4];
    const float* W2 = (const float*)d_in[5];
    const float* b2 = (const float*)d_in[6];
    float* out = (float*)d_out;

    cudaFuncSetAttribute(gemm_hmma<DD, HH, 1>,
                         cudaFuncAttributeMaxDynamicSharedMemorySize, GEMM_SMEM);
    cudaFuncSetAttribute(gemm_hmma<HH, DD, 2>,
                         cudaFuncAttributeMaxDynamicSharedMemorySize, GEMM_SMEM);

    __half *w1h, *w2h, *ah, *hh;
    cudaGetSymbolAddress((void**)&w1h, g_w1h);
    cudaGetSymbolAddress((void**)&w2h, g_w2h);
    cudaGetSymbolAddress((void**)&ah,  g_ah);
    cudaGetSymbolAddress((void**)&hh,  g_hh);

    init_k<<<MAXROWS / 256, 256>>>();
    router_k<<<NTOK / 8, 256>>>(x, Wg, bg);
    scan_k<<<1, 32>>>();
    scatter_k<<<NTOK / 256, 256>>>();
    pregather_k<<<MAXROWS, 256>>>(x);
    // W1[e][D][H] -> [e][H][D] ; W2[e][H][D] -> [e][D][H]
    transconv_k<<<dim3(HH / 32, DD / 32, EE), dim3(32, 8)>>>(W1, w1h, DD, HH);
    transconv_k<<<dim3(DD / 32, HH / 32, EE), dim3(32, 8)>>>(W2, w2h, HH, DD);

    gemm_hmma<DD, HH, 1><<<dim3(HH / NT, MAXROWS / BMT), 128, GEMM_SMEM>>>(
        ah, w1h, b1);
    gemm_hmma<HH, DD, 2><<<dim3(DD / NT, MAXROWS / BMT), 128, GEMM_SMEM>>>(
        hh, w2h, b2);

    combine_k<<<(NTOK * DD / 4) / 256, 256>>>(out);
}